// round 6
// baseline (speedup 1.0000x reference)
#include <cuda_runtime.h>
#include <cuda_bf16.h>

// Problem constants
#define BB   8
#define AA   1024
#define NBN  64
#define NABc 128
#define NFc  128
#define NGc  25
#define NIc  3
#define BA   (BB*AA)        // 8192
#define BANB (BA*NBN)       // 524288
#define CUTF 5.0f

// Scratch (static device globals — allocation-free)
__device__ float g_fij[BANB*NGc];   // gaussian-smeared distances, [pair][25]
__device__ float g_C[BANB];         // cosine cutoff per pair
__device__ float g_y[BA*NFc];       // y = x @ in2f_w
__device__ float g_agg[BA*NFc];     // CFConv aggregate

__device__ __forceinline__ float sspf(float x){
    // shifted softplus: log1p(exp(x)) - log(2), numerically stable
    return fmaxf(x, 0.f) + log1pf(expf(-fabsf(x))) - 0.69314718055994530942f;
}

// ---------------------------------------------------------------------------
// k_prep: distances (with PBC offsets), gaussian smearing, cosine cutoff
// ---------------------------------------------------------------------------
__global__ void k_prep(const float* __restrict__ pos,
                       const float* __restrict__ cell,
                       const float* __restrict__ cofs,
                       const float* __restrict__ nmask,
                       const int*   __restrict__ nbr){
    int p = blockIdx.x * blockDim.x + threadIdx.x;
    if (p >= BANB) return;
    int b = p / (AA*NBN);
    int a = (p / NBN) % AA;
    int j = nbr[p];
    const float* pi = pos + ((size_t)b*AA + a)*3;
    const float* pj = pos + ((size_t)b*AA + j)*3;
    const float* of = cofs + (size_t)p*3;
    const float* cl = cell + (size_t)b*9;
    // pos_j + offset @ cell  (einsum banc,bcd->band)
    float dx = pj[0] + of[0]*cl[0] + of[1]*cl[3] + of[2]*cl[6] - pi[0];
    float dy = pj[1] + of[0]*cl[1] + of[1]*cl[4] + of[2]*cl[7] - pi[1];
    float dz = pj[2] + of[0]*cl[2] + of[1]*cl[5] + of[2]*cl[8] - pi[2];
    float d2 = dx*dx + dy*dy + dz*dz;
    float m  = nmask[p];
    float r  = sqrtf(m > 0.f ? d2 : 1.0f) * m;
    float C  = (r < CUTF) ? 0.5f*(cosf(r*(3.14159265358979323846f/CUTF)) + 1.f) : 0.f;
    g_C[p] = C;
    const float width = CUTF / (float)(NGc-1);
    const float coeff = -0.5f / (width*width);
    #pragma unroll
    for (int g = 0; g < NGc; ++g){
        float d = r - (float)g*width;
        g_fij[(size_t)p*NGc + g] = expf(coeff*d*d);
    }
}

// ---------------------------------------------------------------------------
// k_embed: x = emb[atomic_numbers]
// ---------------------------------------------------------------------------
__global__ void k_embed(const float* __restrict__ emb,
                        const int*   __restrict__ z,
                        float* __restrict__ x){
    int i = blockIdx.x * blockDim.x + threadIdx.x;
    if (i >= BA*NABc) return;
    int a = i / NABc;
    int f = i % NABc;
    x[i] = emb[(size_t)z[a]*NABc + f];
}

// ---------------------------------------------------------------------------
// k_y: y = x @ in2f_w   (8192,128)@(128,128), 8 atoms per block
// ---------------------------------------------------------------------------
__global__ void __launch_bounds__(NFc) k_y(const float* __restrict__ x,
                                           const float* __restrict__ w){
    __shared__ __align__(16) float xs[8*NFc];
    int a0 = blockIdx.x * 8;
    int f  = threadIdx.x;
    for (int t = f; t < 8*NFc; t += NFc) xs[t] = x[(size_t)a0*NFc + t];
    __syncthreads();
    float acc[8];
    #pragma unroll
    for (int j = 0; j < 8; ++j) acc[j] = 0.f;
    for (int k = 0; k < NFc; k += 4){
        float w0 = w[(k+0)*NFc + f];
        float w1 = w[(k+1)*NFc + f];
        float w2 = w[(k+2)*NFc + f];
        float w3 = w[(k+3)*NFc + f];
        #pragma unroll
        for (int j = 0; j < 8; ++j){
            float4 xv = *reinterpret_cast<const float4*>(&xs[j*NFc + k]);
            acc[j] += xv.x*w0 + xv.y*w1 + xv.z*w2 + xv.w*w3;
        }
    }
    #pragma unroll
    for (int j = 0; j < 8; ++j)
        g_y[(size_t)(a0+j)*NFc + f] = acc[j];
}

// ---------------------------------------------------------------------------
// k_conv: filter net (ssp(F@fw1+b1)@fw2+b2)*C fused with CFConv gather+reduce
// 1 block = 1 atom (64 neighbors), 128 threads (thread = filter column f)
// ---------------------------------------------------------------------------
__global__ void __launch_bounds__(NFc) k_conv(const float* __restrict__ fw1,
                                              const float* __restrict__ fb1,
                                              const float* __restrict__ fw2,
                                              const float* __restrict__ fb2,
                                              const int*   __restrict__ nbr,
                                              const float* __restrict__ nmask){
    __shared__ __align__(16) float Fs[NBN*28];   // 25 gaussians padded to 28
    __shared__ __align__(16) float Hs[NBN*NFc];  // ssp(F@fw1+b1)
    __shared__ float Cs[NBN];
    __shared__ float Ms[NBN];
    __shared__ int   Ns[NBN];

    int ba = blockIdx.x;             // flat (b,a)
    int b  = ba / AA;
    int f  = threadIdx.x;
    size_t p0 = (size_t)ba * NBN;

    // Load gaussians (pad cols 25..27 with zero) + cutoff/mask/neighbor idx
    for (int t = f; t < NBN*NGc; t += NFc)
        Fs[(t/NGc)*28 + (t%NGc)] = g_fij[p0*NGc + t];
    for (int t = f; t < NBN*3; t += NFc)
        Fs[(t/3)*28 + 25 + (t%3)] = 0.f;
    if (f < NBN){
        Cs[f] = g_C[p0 + f];
        Ms[f] = nmask[p0 + f];
        Ns[f] = nbr[p0 + f];
    }
    __syncthreads();

    // Step 1: H[n][f] = ssp(b1 + sum_g F[n][g]*fw1[g][f]); fw1 column in regs
    float w1r[28];
    #pragma unroll
    for (int g = 0; g < NGc; ++g) w1r[g] = fw1[g*NFc + f];
    w1r[25] = w1r[26] = w1r[27] = 0.f;
    float b1 = fb1[f];
    for (int n = 0; n < NBN; ++n){
        float acc = b1;
        #pragma unroll
        for (int g = 0; g < 28; g += 4){
            float4 fv = *reinterpret_cast<const float4*>(&Fs[n*28 + g]);
            acc += fv.x*w1r[g] + fv.y*w1r[g+1] + fv.z*w1r[g+2] + fv.w*w1r[g+3];
        }
        Hs[n*NFc + f] = sspf(acc);
    }
    __syncthreads();

    // Step 2: W[n][f] = (b2 + sum_k H[n][k]*fw2[k][f]) * C[n];
    //         agg[f] += W[n][f] * y[neighbor(n)][f] * mask[n]
    const float* yb = g_y + (size_t)b*AA*NFc;
    float b2  = fb2[f];
    float agg = 0.f;
    for (int n0 = 0; n0 < NBN; n0 += 16){
        float wa[16];
        #pragma unroll
        for (int j = 0; j < 16; ++j) wa[j] = b2;
        for (int k = 0; k < NFc; k += 4){
            float w0 = fw2[(k+0)*NFc + f];
            float w1 = fw2[(k+1)*NFc + f];
            float w2 = fw2[(k+2)*NFc + f];
            float w3 = fw2[(k+3)*NFc + f];
            #pragma unroll
            for (int j = 0; j < 16; ++j){
                float4 h = *reinterpret_cast<const float4*>(&Hs[(n0+j)*NFc + k]);
                wa[j] += h.x*w0 + h.y*w1 + h.z*w2 + h.w*w3;
            }
        }
        #pragma unroll
        for (int j = 0; j < 16; ++j){
            int n = n0 + j;
            float W = wa[j] * Cs[n];
            float yv = yb[(size_t)Ns[n]*NFc + f];
            agg += W * yv * Ms[n];
        }
    }
    g_agg[(size_t)ba*NFc + f] = agg;
}

// ---------------------------------------------------------------------------
// k_out: v = ssp(agg @ f2out_w + f2out_b) @ dense_w + dense_b;  x += v
// 8 atoms per block
// ---------------------------------------------------------------------------
__global__ void __launch_bounds__(NFc) k_out(const float* __restrict__ f2w,
                                             const float* __restrict__ f2b,
                                             const float* __restrict__ dw,
                                             const float* __restrict__ db,
                                             float* __restrict__ x){
    __shared__ __align__(16) float as_[8*NFc];
    __shared__ __align__(16) float ts[8*NFc];
    int a0 = blockIdx.x * 8;
    int f  = threadIdx.x;
    for (int t = f; t < 8*NFc; t += NFc) as_[t] = g_agg[(size_t)a0*NFc + t];
    __syncthreads();

    float acc[8];
    float bb1 = f2b[f];
    #pragma unroll
    for (int j = 0; j < 8; ++j) acc[j] = bb1;
    for (int k = 0; k < NFc; k += 4){
        float w0 = f2w[(k+0)*NFc + f];
        float w1 = f2w[(k+1)*NFc + f];
        float w2 = f2w[(k+2)*NFc + f];
        float w3 = f2w[(k+3)*NFc + f];
        #pragma unroll
        for (int j = 0; j < 8; ++j){
            float4 av = *reinterpret_cast<const float4*>(&as_[j*NFc + k]);
            acc[j] += av.x*w0 + av.y*w1 + av.z*w2 + av.w*w3;
        }
    }
    #pragma unroll
    for (int j = 0; j < 8; ++j) ts[j*NFc + f] = sspf(acc[j]);
    __syncthreads();

    float bb2 = db[f];
    #pragma unroll
    for (int j = 0; j < 8; ++j) acc[j] = bb2;
    for (int k = 0; k < NFc; k += 4){
        float w0 = dw[(k+0)*NFc + f];
        float w1 = dw[(k+1)*NFc + f];
        float w2 = dw[(k+2)*NFc + f];
        float w3 = dw[(k+3)*NFc + f];
        #pragma unroll
        for (int j = 0; j < 8; ++j){
            float4 tv = *reinterpret_cast<const float4*>(&ts[j*NFc + k]);
            acc[j] += tv.x*w0 + tv.y*w1 + tv.z*w2 + tv.w*w3;
        }
    }
    #pragma unroll
    for (int j = 0; j < 8; ++j)
        x[(size_t)(a0+j)*NFc + f] += acc[j];
}

// ---------------------------------------------------------------------------
extern "C" void kernel_launch(void* const* d_in, const int* in_sizes, int n_in,
                              void* d_out, int out_size){
    const float* positions = (const float*)d_in[0];
    const float* cell      = (const float*)d_in[1];
    const float* cofs      = (const float*)d_in[2];
    const float* nmask     = (const float*)d_in[3];
    // d_in[4] atom_mask: unused by reference
    const float* emb       = (const float*)d_in[5];
    const float* fw1       = (const float*)d_in[6];
    const float* fb1       = (const float*)d_in[7];
    const float* fw2       = (const float*)d_in[8];
    const float* fb2       = (const float*)d_in[9];
    const float* in2f_w    = (const float*)d_in[10];
    const float* f2out_w   = (const float*)d_in[11];
    const float* f2out_b   = (const float*)d_in[12];
    const float* dense_w   = (const float*)d_in[13];
    const float* dense_b   = (const float*)d_in[14];
    const int*   znum      = (const int*)  d_in[15];
    const int*   nbr       = (const int*)  d_in[16];
    float* x = (float*)d_out;

    k_prep<<<(BANB + 255)/256, 256>>>(positions, cell, cofs, nmask, nbr);
    k_embed<<<(BA*NABc + 255)/256, 256>>>(emb, znum, x);

    for (int i = 0; i < NIc; ++i){
        k_y   <<<BA/8, NFc>>>(x, in2f_w + (size_t)i*NABc*NFc);
        k_conv<<<BA,   NFc>>>(fw1 + (size_t)i*NGc*NFc, fb1 + (size_t)i*NFc,
                              fw2 + (size_t)i*NFc*NFc, fb2 + (size_t)i*NFc,
                              nbr, nmask);
        k_out <<<BA/8, NFc>>>(f2out_w + (size_t)i*NFc*NABc, f2out_b + (size_t)i*NABc,
                              dense_w + (size_t)i*NABc*NABc, dense_b + (size_t)i*NABc,
                              x);
    }
}

// round 12
// speedup vs baseline: 1.0564x; 1.0564x over previous
#include <cuda_runtime.h>
#include <cuda_bf16.h>
#include <cstdint>

// Problem constants
#define BB   8
#define AA   1024
#define NBN  64
#define NABc 128
#define NFc  128
#define NGc  25
#define NIc  3
#define BA   (BB*AA)        // 8192
#define BANB (BA*NBN)       // 524288
#define CUTF 5.0f

// Scratch (static device globals — allocation-free)
__device__ float g_fij[BANB*NGc];   // gaussian-smeared distances, [pair][25]
__device__ float g_C[BANB];         // cosine cutoff per pair
__device__ float g_y[BA*NFc];       // y = x @ in2f_w
__device__ float g_agg[BA*NFc];     // CFConv aggregate
// fw2^T in mma-fragment order, tf32 hi/lo: [i][mtile8][kstep16][lane32][reg4]
__device__ __align__(16) uint32_t g_afh[NIc*8*16*32*4];
__device__ __align__(16) uint32_t g_afl[NIc*8*16*32*4];

__device__ __forceinline__ float sspf(float x){
    // accurate shifted softplus (used in k_out)
    return fmaxf(x, 0.f) + log1pf(expf(-fabsf(x))) - 0.69314718055994530942f;
}
__device__ __forceinline__ float sspf_fast(float x){
    // MUFU-based shifted softplus (rel err ~1e-6)
    float e = __expf(-fabsf(x));
    return fmaxf(x, 0.f) + __logf(1.0f + e) - 0.69314718055994530942f;
}
__device__ __forceinline__ uint32_t f2t(float x){
    uint32_t r; asm("cvt.rna.tf32.f32 %0, %1;" : "=r"(r) : "f"(x)); return r;
}
// D(16x8) += A(16x8 row, tf32) * B(8x8 col, tf32)   [family-wide sm_80+ mma]
__device__ __forceinline__ void mma8(float* d, const uint32_t* a, const uint32_t* b){
    asm volatile(
        "mma.sync.aligned.m16n8k8.row.col.f32.tf32.tf32.f32 "
        "{%0,%1,%2,%3}, {%4,%5,%6,%7}, {%8,%9}, {%0,%1,%2,%3};"
        : "+f"(d[0]), "+f"(d[1]), "+f"(d[2]), "+f"(d[3])
        : "r"(a[0]), "r"(a[1]), "r"(a[2]), "r"(a[3]), "r"(b[0]), "r"(b[1]));
}

// ---------------------------------------------------------------------------
// k_prep: distances, gaussian smearing, cosine cutoff
// ---------------------------------------------------------------------------
__global__ void k_prep(const float* __restrict__ pos,
                       const float* __restrict__ cell,
                       const float* __restrict__ cofs,
                       const float* __restrict__ nmask,
                       const int*   __restrict__ nbr){
    int p = blockIdx.x * blockDim.x + threadIdx.x;
    if (p >= BANB) return;
    int b = p / (AA*NBN);
    int a = (p / NBN) % AA;
    int j = nbr[p];
    const float* pi = pos + ((size_t)b*AA + a)*3;
    const float* pj = pos + ((size_t)b*AA + j)*3;
    const float* of = cofs + (size_t)p*3;
    const float* cl = cell + (size_t)b*9;
    float dx = pj[0] + of[0]*cl[0] + of[1]*cl[3] + of[2]*cl[6] - pi[0];
    float dy = pj[1] + of[0]*cl[1] + of[1]*cl[4] + of[2]*cl[7] - pi[1];
    float dz = pj[2] + of[0]*cl[2] + of[1]*cl[5] + of[2]*cl[8] - pi[2];
    float d2 = dx*dx + dy*dy + dz*dz;
    float m  = nmask[p];
    float r  = sqrtf(m > 0.f ? d2 : 1.0f) * m;
    float C  = (r < CUTF) ? 0.5f*(cosf(r*(3.14159265358979323846f/CUTF)) + 1.f) : 0.f;
    g_C[p] = C;
    const float width = CUTF / (float)(NGc-1);
    const float coeff = -0.5f / (width*width);
    #pragma unroll
    for (int g = 0; g < NGc; ++g){
        float d = r - (float)g*width;
        g_fij[(size_t)p*NGc + g] = expf(coeff*d*d);
    }
}

// ---------------------------------------------------------------------------
// k_wt: fw2 -> A-operand fragments (fw2^T as 128f x 128k), tf32 hi/lo.
// mma m16n8k8 A layout: a0:(g,t) a1:(g+8,t) a2:(g,t+4) a3:(g+8,t+4),
// g=lane>>2, t=lane&3. Linear index = (((i*8+m)*16+s)*32+l)*4+r.
// ---------------------------------------------------------------------------
__global__ void k_wt(const float* __restrict__ fw2){
    int idx = blockIdx.x*blockDim.x + threadIdx.x;
    if (idx >= NIc*8*16*32*4) return;
    int r = idx & 3;
    int l = (idx >> 2) & 31;
    int s = (idx >> 7) & 15;
    int m = (idx >> 11) & 7;
    int i = idx >> 14;
    int g = l >> 2, t = l & 3;
    int f = m*16 + g + (r & 1)*8;       // A row = filter index
    int k = s*8 + t + ((r & 2) ? 4 : 0); // A col = k index
    float v = fw2[((size_t)i*NFc + k)*NFc + f];  // fw2[i][k][f] = A[f][k]
    uint32_t hb = f2t(v);
    float lo = v - __uint_as_float(hb);
    g_afh[idx] = hb;
    g_afl[idx] = f2t(lo);
}

// ---------------------------------------------------------------------------
// k_embed: x = emb[atomic_numbers]
// ---------------------------------------------------------------------------
__global__ void k_embed(const float* __restrict__ emb,
                        const int*   __restrict__ z,
                        float* __restrict__ x){
    int i = blockIdx.x * blockDim.x + threadIdx.x;
    if (i >= BA*NABc) return;
    int a = i / NABc;
    int f = i % NABc;
    x[i] = emb[(size_t)z[a]*NABc + f];
}

// ---------------------------------------------------------------------------
// k_y: y = x @ in2f_w   (8192,128)@(128,128), 8 atoms per block
// ---------------------------------------------------------------------------
__global__ void __launch_bounds__(NFc) k_y(const float* __restrict__ x,
                                           const float* __restrict__ w){
    __shared__ __align__(16) float xs[8*NFc];
    int a0 = blockIdx.x * 8;
    int f  = threadIdx.x;
    for (int t = f; t < 8*NFc; t += NFc) xs[t] = x[(size_t)a0*NFc + t];
    __syncthreads();
    float acc[8];
    #pragma unroll
    for (int j = 0; j < 8; ++j) acc[j] = 0.f;
    for (int k = 0; k < NFc; k += 4){
        float w0 = w[(k+0)*NFc + f];
        float w1 = w[(k+1)*NFc + f];
        float w2 = w[(k+2)*NFc + f];
        float w3 = w[(k+3)*NFc + f];
        #pragma unroll
        for (int j = 0; j < 8; ++j){
            float4 xv = *reinterpret_cast<const float4*>(&xs[j*NFc + k]);
            acc[j] += xv.x*w0 + xv.y*w1 + xv.z*w2 + xv.w*w3;
        }
    }
    #pragma unroll
    for (int j = 0; j < 8; ++j)
        g_y[(size_t)(a0+j)*NFc + f] = acc[j];
}

// ---------------------------------------------------------------------------
// k_conv_m: CFConv via warp-level tf32 HMMA (3x split for fp32 accuracy).
// 1 block = 1 atom (64 neighbor rows), 128 threads / 4 warps.
//  step1 (FMA):  H[n][k] = ssp_fast(F@fw1+b1) -> smem in B-fragment order (hi/lo)
//  step2 (HMMA): D[f][n] = sum_k A[f][k]*H[n][k], warp w owns f rows [32w,32w+32)
//  stage:        D -> smem Ws[n][f] (aliased over dead B region)
//  epilogue:     agg[f] = sum_n (D+b2)*C[n]*M[n]*y[nbr[n]][f]
// smem floats: Fs 1792 | CM 64 | NS 64 | BH 8192 u32 | BL 8192 u32  = 73216 B
// ---------------------------------------------------------------------------
#define SMF_FS   0
#define SMF_CM   1792
#define SMF_NS   1856
#define SMF_B    1920
#define SM_TOTB  (SMF_B*4 + 65536)

__global__ void __launch_bounds__(128) k_conv_m(int inter,
        const float* __restrict__ fw1, const float* __restrict__ fb1,
        const float* __restrict__ fb2,
        const int*   __restrict__ nbr, const float* __restrict__ nmask){
    extern __shared__ float sm[];
    float*    Fs = sm + SMF_FS;
    float*    CM = sm + SMF_CM;
    int*      NS = (int*)(sm + SMF_NS);
    uint32_t* BH = (uint32_t*)(sm + SMF_B);
    uint32_t* BL = BH + 8192;
    float*    Ws = (float*)BH;           // alias: B region dead after mma

    int tid = threadIdx.x, wid = tid >> 5, lane = tid & 31;
    int ba = blockIdx.x;                 // flat (b,a)
    int b  = ba >> 10;
    size_t p0 = (size_t)ba * NBN;

    // Loads: gaussians (pad 25->28), C*mask, neighbor idx
    for (int t = tid; t < NBN*NGc; t += 128)
        Fs[(t/NGc)*28 + (t%NGc)] = g_fij[p0*NGc + t];
    for (int t = tid; t < NBN*3; t += 128)
        Fs[(t/3)*28 + 25 + (t%3)] = 0.f;
    if (tid < NBN){
        CM[tid] = g_C[p0 + tid] * nmask[p0 + tid];
        NS[tid] = nbr[p0 + tid];
    }
    __syncthreads();

    // ---- step 1: H column k=tid over 64 neighbors; write B-fragment order ----
    float w1r[28];
    #pragma unroll
    for (int g = 0; g < NGc; ++g) w1r[g] = fw1[g*NFc + tid];
    w1r[25] = w1r[26] = w1r[27] = 0.f;
    float b1 = fb1[tid];
    int ks_ = tid >> 3, t_ = tid & 3, slot = (tid >> 2) & 1;
    for (int n = 0; n < NBN; ++n){
        const float4* fr = reinterpret_cast<const float4*>(Fs + n*28);
        float acc = b1;
        #pragma unroll
        for (int g = 0; g < 7; ++g){
            float4 v = fr[g];
            acc += v.x*w1r[4*g] + v.y*w1r[4*g+1] + v.z*w1r[4*g+2] + v.w*w1r[4*g+3];
        }
        float h = sspf_fast(acc);
        uint32_t hb = f2t(h);
        float lo = h - __uint_as_float(hb);
        // b-frag: lane = (n&7)*4 + (k&3); b0/b1 = k&4; per (ntile,kstep) 32 lanes x2
        int idx = (((n >> 3)*16 + ks_)*32 + (n & 7)*4 + t_)*2 + slot;
        BH[idx] = hb;
        BL[idx] = f2t(lo);
    }
    __syncthreads();

    // ---- step 2: HMMA. warp wid: mtiles {2w,2w+1}; all 8 ntiles; 16 ksteps ----
    float acc[2][8][4];
    #pragma unroll
    for (int mt = 0; mt < 2; ++mt)
        #pragma unroll
        for (int nt = 0; nt < 8; ++nt)
            #pragma unroll
            for (int r = 0; r < 4; ++r) acc[mt][nt][r] = 0.f;

    const uint4* Ah = reinterpret_cast<const uint4*>(g_afh + (size_t)inter*16384);
    const uint4* Al = reinterpret_cast<const uint4*>(g_afl + (size_t)inter*16384);
    #pragma unroll 4
    for (int s = 0; s < 16; ++s){
        uint4 ah[2], al[2];
        #pragma unroll
        for (int mt = 0; mt < 2; ++mt){
            int ai = ((2*wid + mt)*16 + s)*32 + lane;
            ah[mt] = Ah[ai];
            al[mt] = Al[ai];
        }
        #pragma unroll
        for (int nt = 0; nt < 8; ++nt){
            int bi = ((nt*16 + s)*32 + lane)*2;
            uint2 bh = *reinterpret_cast<const uint2*>(&BH[bi]);
            uint2 bl = *reinterpret_cast<const uint2*>(&BL[bi]);
            uint32_t bhr[2] = {bh.x, bh.y};
            uint32_t blr[2] = {bl.x, bl.y};
            #pragma unroll
            for (int mt = 0; mt < 2; ++mt){
                mma8(acc[mt][nt], &ah[mt].x, bhr);  // hi*hi
                mma8(acc[mt][nt], &ah[mt].x, blr);  // hi*lo
                mma8(acc[mt][nt], &al[mt].x, bhr);  // lo*hi
            }
        }
    }
    __syncthreads();   // all warps done reading BH/BL before aliasing as Ws

    // ---- stage D into Ws[n][f] ----
    {
        int g = lane >> 2, t4 = lane & 3;
        #pragma unroll
        for (int mt = 0; mt < 2; ++mt){
            int f = 32*wid + mt*16 + g;
            #pragma unroll
            for (int nt = 0; nt < 8; ++nt){
                int n = nt*8 + t4*2;
                Ws[n*NFc + f]         = acc[mt][nt][0];
                Ws[(n+1)*NFc + f]     = acc[mt][nt][1];
                Ws[n*NFc + f + 8]     = acc[mt][nt][2];
                Ws[(n+1)*NFc + f + 8] = acc[mt][nt][3];
            }
        }
    }
    __syncthreads();

    // ---- epilogue: thread = f; coalesced y gathers ----
    float b2 = fb2[tid];
    const float* yb = g_y + (size_t)b*AA*NFc;
    float agg = 0.f;
    #pragma unroll 4
    for (int n = 0; n < NBN; ++n){
        float w = (Ws[n*NFc + tid] + b2) * CM[n];
        agg += w * yb[(size_t)NS[n]*NFc + tid];
    }
    g_agg[(size_t)ba*NFc + tid] = agg;
}

// ---------------------------------------------------------------------------
// k_out: v = ssp(agg @ f2out_w + f2out_b) @ dense_w + dense_b;  x += v
// ---------------------------------------------------------------------------
__global__ void __launch_bounds__(NFc) k_out(const float* __restrict__ f2w,
                                             const float* __restrict__ f2b,
                                             const float* __restrict__ dw,
                                             const float* __restrict__ db,
                                             float* __restrict__ x){
    __shared__ __align__(16) float as_[8*NFc];
    __shared__ __align__(16) float ts[8*NFc];
    int a0 = blockIdx.x * 8;
    int f  = threadIdx.x;
    for (int t = f; t < 8*NFc; t += NFc) as_[t] = g_agg[(size_t)a0*NFc + t];
    __syncthreads();

    float acc[8];
    float bb1 = f2b[f];
    #pragma unroll
    for (int j = 0; j < 8; ++j) acc[j] = bb1;
    for (int k = 0; k < NFc; k += 4){
        float w0 = f2w[(k+0)*NFc + f];
        float w1 = f2w[(k+1)*NFc + f];
        float w2 = f2w[(k+2)*NFc + f];
        float w3 = f2w[(k+3)*NFc + f];
        #pragma unroll
        for (int j = 0; j < 8; ++j){
            float4 av = *reinterpret_cast<const float4*>(&as_[j*NFc + k]);
            acc[j] += av.x*w0 + av.y*w1 + av.z*w2 + av.w*w3;
        }
    }
    #pragma unroll
    for (int j = 0; j < 8; ++j) ts[j*NFc + f] = sspf(acc[j]);
    __syncthreads();

    float bb2 = db[f];
    #pragma unroll
    for (int j = 0; j < 8; ++j) acc[j] = bb2;
    for (int k = 0; k < NFc; k += 4){
        float w0 = dw[(k+0)*NFc + f];
        float w1 = dw[(k+1)*NFc + f];
        float w2 = dw[(k+2)*NFc + f];
        float w3 = dw[(k+3)*NFc + f];
        #pragma unroll
        for (int j = 0; j < 8; ++j){
            float4 tv = *reinterpret_cast<const float4*>(&ts[j*NFc + k]);
            acc[j] += tv.x*w0 + tv.y*w1 + tv.z*w2 + tv.w*w3;
        }
    }
    #pragma unroll
    for (int j = 0; j < 8; ++j)
        x[(size_t)(a0+j)*NFc + f] += acc[j];
}

// ---------------------------------------------------------------------------
extern "C" void kernel_launch(void* const* d_in, const int* in_sizes, int n_in,
                              void* d_out, int out_size){
    const float* positions = (const float*)d_in[0];
    const float* cell      = (const float*)d_in[1];
    const float* cofs      = (const float*)d_in[2];
    const float* nmask     = (const float*)d_in[3];
    // d_in[4] atom_mask: unused by reference
    const float* emb       = (const float*)d_in[5];
    const float* fw1       = (const float*)d_in[6];
    const float* fb1       = (const float*)d_in[7];
    const float* fw2       = (const float*)d_in[8];
    const float* fb2       = (const float*)d_in[9];
    const float* in2f_w    = (const float*)d_in[10];
    const float* f2out_w   = (const float*)d_in[11];
    const float* f2out_b   = (const float*)d_in[12];
    const float* dense_w   = (const float*)d_in[13];
    const float* dense_b   = (const float*)d_in[14];
    const int*   znum      = (const int*)  d_in[15];
    const int*   nbr       = (const int*)  d_in[16];
    float* x = (float*)d_out;

    static int smem_set = 0;
    if (!smem_set){
        cudaFuncSetAttribute(k_conv_m, cudaFuncAttributeMaxDynamicSharedMemorySize, SM_TOTB);
        smem_set = 1;
    }

    k_prep<<<(BANB + 255)/256, 256>>>(positions, cell, cofs, nmask, nbr);
    k_wt  <<<(NIc*8*16*32*4 + 255)/256, 256>>>(fw2);
    k_embed<<<(BA*NABc + 255)/256, 256>>>(emb, znum, x);

    for (int i = 0; i < NIc; ++i){
        k_y     <<<BA/8, NFc>>>(x, in2f_w + (size_t)i*NABc*NFc);
        k_conv_m<<<BA,   128, SM_TOTB>>>(i,
                              fw1 + (size_t)i*NGc*NFc, fb1 + (size_t)i*NFc,
                              fb2 + (size_t)i*NFc,
                              nbr, nmask);
        k_out   <<<BA/8, NFc>>>(f2out_w + (size_t)i*NFc*NABc, f2out_b + (size_t)i*NABc,
                              dense_w + (size_t)i*NABc*NABc, dense_b + (size_t)i*NABc,
                              x);
    }
}

// round 15
// speedup vs baseline: 1.5166x; 1.4356x over previous
#include <cuda_runtime.h>
#include <cuda_bf16.h>
#include <cstdint>

// Problem constants
#define BB   8
#define AA   1024
#define NBN  64
#define NABc 128
#define NFc  128
#define NGc  25
#define NIc  3
#define BA   (BB*AA)        // 8192
#define BANB (BA*NBN)       // 524288
#define CUTF 5.0f

// Scratch (static device globals — allocation-free)
__device__ float g_fij[BANB*NGc];   // gaussian-smeared distances, [pair][25]
__device__ float g_C[BANB];         // cosine cutoff per pair
__device__ float g_y[BA*NFc];       // y = x @ in2f_w
__device__ float g_agg[BA*NFc];     // CFConv aggregate
// fw2^T in mma-fragment order, tf32: [i][mtile8][kstep16][lane32][reg4]
__device__ __align__(16) uint32_t g_afh[NIc*8*16*32*4];

__device__ __forceinline__ float sspf(float x){
    // accurate shifted softplus (used in k_out)
    return fmaxf(x, 0.f) + log1pf(expf(-fabsf(x))) - 0.69314718055994530942f;
}
__device__ __forceinline__ float sspf_fast(float x){
    // MUFU-based shifted softplus (rel err ~1e-6)
    float e = __expf(-fabsf(x));
    return fmaxf(x, 0.f) + __logf(1.0f + e) - 0.69314718055994530942f;
}
__device__ __forceinline__ uint32_t f2t(float x){
    uint32_t r; asm("cvt.rna.tf32.f32 %0, %1;" : "=r"(r) : "f"(x)); return r;
}
// D(16x8) += A(16x8 row, tf32) * B(8x8 col, tf32)   [family-wide sm_80+ mma]
__device__ __forceinline__ void mma8(float* d, const uint32_t* a, const uint32_t* b){
    asm volatile(
        "mma.sync.aligned.m16n8k8.row.col.f32.tf32.tf32.f32 "
        "{%0,%1,%2,%3}, {%4,%5,%6,%7}, {%8,%9}, {%0,%1,%2,%3};"
        : "+f"(d[0]), "+f"(d[1]), "+f"(d[2]), "+f"(d[3])
        : "r"(a[0]), "r"(a[1]), "r"(a[2]), "r"(a[3]), "r"(b[0]), "r"(b[1]));
}

// ---------------------------------------------------------------------------
// k_prep: distances, gaussian smearing, cosine cutoff
// ---------------------------------------------------------------------------
__global__ void k_prep(const float* __restrict__ pos,
                       const float* __restrict__ cell,
                       const float* __restrict__ cofs,
                       const float* __restrict__ nmask,
                       const int*   __restrict__ nbr){
    int p = blockIdx.x * blockDim.x + threadIdx.x;
    if (p >= BANB) return;
    int b = p / (AA*NBN);
    int a = (p / NBN) % AA;
    int j = nbr[p];
    const float* pi = pos + ((size_t)b*AA + a)*3;
    const float* pj = pos + ((size_t)b*AA + j)*3;
    const float* of = cofs + (size_t)p*3;
    const float* cl = cell + (size_t)b*9;
    float dx = pj[0] + of[0]*cl[0] + of[1]*cl[3] + of[2]*cl[6] - pi[0];
    float dy = pj[1] + of[0]*cl[1] + of[1]*cl[4] + of[2]*cl[7] - pi[1];
    float dz = pj[2] + of[0]*cl[2] + of[1]*cl[5] + of[2]*cl[8] - pi[2];
    float d2 = dx*dx + dy*dy + dz*dz;
    float m  = nmask[p];
    float r  = sqrtf(m > 0.f ? d2 : 1.0f) * m;
    float C  = (r < CUTF) ? 0.5f*(cosf(r*(3.14159265358979323846f/CUTF)) + 1.f) : 0.f;
    g_C[p] = C;
    const float width = CUTF / (float)(NGc-1);
    const float coeff = -0.5f / (width*width);
    #pragma unroll
    for (int g = 0; g < NGc; ++g){
        float d = r - (float)g*width;
        g_fij[(size_t)p*NGc + g] = expf(coeff*d*d);
    }
}

// ---------------------------------------------------------------------------
// k_wt: fw2 -> A-operand fragments (fw2^T as 128f x 128k), tf32.
// mma m16n8k8 A layout: a0:(g,t) a1:(g+8,t) a2:(g,t+4) a3:(g+8,t+4),
// g=lane>>2, t=lane&3. Linear index = (((i*8+m)*16+s)*32+l)*4+r.
// ---------------------------------------------------------------------------
__global__ void k_wt(const float* __restrict__ fw2){
    int idx = blockIdx.x*blockDim.x + threadIdx.x;
    if (idx >= NIc*8*16*32*4) return;
    int r = idx & 3;
    int l = (idx >> 2) & 31;
    int s = (idx >> 7) & 15;
    int m = (idx >> 11) & 7;
    int i = idx >> 14;
    int g = l >> 2, t = l & 3;
    int f = m*16 + g + (r & 1)*8;        // A row = filter index
    int k = s*8 + t + ((r & 2) ? 4 : 0); // A col = k index
    g_afh[idx] = f2t(fw2[((size_t)i*NFc + k)*NFc + f]);
}

// ---------------------------------------------------------------------------
// k_embed: x = emb[atomic_numbers]
// ---------------------------------------------------------------------------
__global__ void k_embed(const float* __restrict__ emb,
                        const int*   __restrict__ z,
                        float* __restrict__ x){
    int i = blockIdx.x * blockDim.x + threadIdx.x;
    if (i >= BA*NABc) return;
    int a = i / NABc;
    int f = i % NABc;
    x[i] = emb[(size_t)z[a]*NABc + f];
}

// ---------------------------------------------------------------------------
// k_y: y = x @ in2f_w   (8192,128)@(128,128), 8 atoms per block
// ---------------------------------------------------------------------------
__global__ void __launch_bounds__(NFc) k_y(const float* __restrict__ x,
                                           const float* __restrict__ w){
    __shared__ __align__(16) float xs[8*NFc];
    int a0 = blockIdx.x * 8;
    int f  = threadIdx.x;
    for (int t = f; t < 8*NFc; t += NFc) xs[t] = x[(size_t)a0*NFc + t];
    __syncthreads();
    float acc[8];
    #pragma unroll
    for (int j = 0; j < 8; ++j) acc[j] = 0.f;
    for (int k = 0; k < NFc; k += 4){
        float w0 = w[(k+0)*NFc + f];
        float w1 = w[(k+1)*NFc + f];
        float w2 = w[(k+2)*NFc + f];
        float w3 = w[(k+3)*NFc + f];
        #pragma unroll
        for (int j = 0; j < 8; ++j){
            float4 xv = *reinterpret_cast<const float4*>(&xs[j*NFc + k]);
            acc[j] += xv.x*w0 + xv.y*w1 + xv.z*w2 + xv.w*w3;
        }
    }
    #pragma unroll
    for (int j = 0; j < 8; ++j)
        g_y[(size_t)(a0+j)*NFc + f] = acc[j];
}

// ---------------------------------------------------------------------------
// k_conv_m: CFConv via warp-level tf32 HMMA (single-pass tf32).
// 1 block = 1 atom (64 neighbor rows), 128 threads / 4 warps.
//  step1 (FMA):  H[n][k] = ssp_fast(F@fw1+b1) -> smem in B-fragment order (tf32)
//  step2 (HMMA): D[f][n] = sum_k A[f][k]*H[n][k], warp w owns f rows [32w,32w+32)
//  stage:        D -> smem Ws[n][f] (aliased over dead B region)
//  epilogue:     agg[f] = sum_n (D+b2)*C[n]*M[n]*y[nbr[n]][f]
// smem floats: Fs 1792 | CM 64 | NS 64 | BH 8192 u32  = 40448 B
// ---------------------------------------------------------------------------
#define SMF_FS   0
#define SMF_CM   1792
#define SMF_NS   1856
#define SMF_B    1920
#define SM_TOTB  (SMF_B*4 + 32768)

__global__ void __launch_bounds__(128) k_conv_m(int inter,
        const float* __restrict__ fw1, const float* __restrict__ fb1,
        const float* __restrict__ fb2,
        const int*   __restrict__ nbr, const float* __restrict__ nmask){
    extern __shared__ float sm[];
    float*    Fs = sm + SMF_FS;
    float*    CM = sm + SMF_CM;
    int*      NS = (int*)(sm + SMF_NS);
    uint32_t* BH = (uint32_t*)(sm + SMF_B);
    float*    Ws = (float*)BH;           // alias: B region dead after mma

    int tid = threadIdx.x, wid = tid >> 5, lane = tid & 31;
    int ba = blockIdx.x;                 // flat (b,a)
    int b  = ba >> 10;
    size_t p0 = (size_t)ba * NBN;

    // Loads: gaussians (pad 25->28), C*mask, neighbor idx
    for (int t = tid; t < NBN*NGc; t += 128)
        Fs[(t/NGc)*28 + (t%NGc)] = g_fij[p0*NGc + t];
    for (int t = tid; t < NBN*3; t += 128)
        Fs[(t/3)*28 + 25 + (t%3)] = 0.f;
    if (tid < NBN){
        CM[tid] = g_C[p0 + tid] * nmask[p0 + tid];
        NS[tid] = nbr[p0 + tid];
    }
    __syncthreads();

    // ---- step 1: H column k=tid over 64 neighbors; write B-fragment order ----
    float w1r[28];
    #pragma unroll
    for (int g = 0; g < NGc; ++g) w1r[g] = fw1[g*NFc + tid];
    w1r[25] = w1r[26] = w1r[27] = 0.f;
    float b1 = fb1[tid];
    int ks_ = tid >> 3, t_ = tid & 3, slot = (tid >> 2) & 1;
    for (int n = 0; n < NBN; ++n){
        const float4* fr = reinterpret_cast<const float4*>(Fs + n*28);
        float acc = b1;
        #pragma unroll
        for (int g = 0; g < 7; ++g){
            float4 v = fr[g];
            acc += v.x*w1r[4*g] + v.y*w1r[4*g+1] + v.z*w1r[4*g+2] + v.w*w1r[4*g+3];
        }
        float h = sspf_fast(acc);
        // b-frag: lane = (n&7)*4 + (k&3); b0/b1 = k&4; per (ntile,kstep) 32 lanes x2
        int idx = (((n >> 3)*16 + ks_)*32 + (n & 7)*4 + t_)*2 + slot;
        BH[idx] = f2t(h);
    }
    __syncthreads();

    // ---- step 2: HMMA. warp wid: mtiles {2w,2w+1}; all 8 ntiles; 16 ksteps ----
    float acc[2][8][4];
    #pragma unroll
    for (int mt = 0; mt < 2; ++mt)
        #pragma unroll
        for (int nt = 0; nt < 8; ++nt)
            #pragma unroll
            for (int r = 0; r < 4; ++r) acc[mt][nt][r] = 0.f;

    const uint4* Ah = reinterpret_cast<const uint4*>(g_afh + (size_t)inter*16384);
    #pragma unroll 4
    for (int s = 0; s < 16; ++s){
        uint4 ah[2];
        #pragma unroll
        for (int mt = 0; mt < 2; ++mt)
            ah[mt] = Ah[((2*wid + mt)*16 + s)*32 + lane];
        #pragma unroll
        for (int nt = 0; nt < 8; ++nt){
            int bi = ((nt*16 + s)*32 + lane)*2;
            uint2 bh = *reinterpret_cast<const uint2*>(&BH[bi]);
            uint32_t bhr[2] = {bh.x, bh.y};
            #pragma unroll
            for (int mt = 0; mt < 2; ++mt)
                mma8(acc[mt][nt], &ah[mt].x, bhr);
        }
    }
    __syncthreads();   // all warps done reading BH before aliasing as Ws

    // ---- stage D into Ws[n][f] ----
    {
        int g = lane >> 2, t4 = lane & 3;
        #pragma unroll
        for (int mt = 0; mt < 2; ++mt){
            int f = 32*wid + mt*16 + g;
            #pragma unroll
            for (int nt = 0; nt < 8; ++nt){
                int n = nt*8 + t4*2;
                Ws[n*NFc + f]         = acc[mt][nt][0];
                Ws[(n+1)*NFc + f]     = acc[mt][nt][1];
                Ws[n*NFc + f + 8]     = acc[mt][nt][2];
                Ws[(n+1)*NFc + f + 8] = acc[mt][nt][3];
            }
        }
    }
    __syncthreads();

    // ---- epilogue: thread = f; coalesced y gathers ----
    float b2 = fb2[tid];
    const float* yb = g_y + (size_t)b*AA*NFc;
    float agg = 0.f;
    #pragma unroll 4
    for (int n = 0; n < NBN; ++n){
        float w = (Ws[n*NFc + tid] + b2) * CM[n];
        agg += w * yb[(size_t)NS[n]*NFc + tid];
    }
    g_agg[(size_t)ba*NFc + tid] = agg;
}

// ---------------------------------------------------------------------------
// k_out: v = ssp(agg @ f2out_w + f2out_b) @ dense_w + dense_b;  x += v
// ---------------------------------------------------------------------------
__global__ void __launch_bounds__(NFc) k_out(const float* __restrict__ f2w,
                                             const float* __restrict__ f2b,
                                             const float* __restrict__ dw,
                                             const float* __restrict__ db,
                                             float* __restrict__ x){
    __shared__ __align__(16) float as_[8*NFc];
    __shared__ __align__(16) float ts[8*NFc];
    int a0 = blockIdx.x * 8;
    int f  = threadIdx.x;
    for (int t = f; t < 8*NFc; t += NFc) as_[t] = g_agg[(size_t)a0*NFc + t];
    __syncthreads();

    float acc[8];
    float bb1 = f2b[f];
    #pragma unroll
    for (int j = 0; j < 8; ++j) acc[j] = bb1;
    for (int k = 0; k < NFc; k += 4){
        float w0 = f2w[(k+0)*NFc + f];
        float w1 = f2w[(k+1)*NFc + f];
        float w2 = f2w[(k+2)*NFc + f];
        float w3 = f2w[(k+3)*NFc + f];
        #pragma unroll
        for (int j = 0; j < 8; ++j){
            float4 av = *reinterpret_cast<const float4*>(&as_[j*NFc + k]);
            acc[j] += av.x*w0 + av.y*w1 + av.z*w2 + av.w*w3;
        }
    }
    #pragma unroll
    for (int j = 0; j < 8; ++j) ts[j*NFc + f] = sspf(acc[j]);
    __syncthreads();

    float bb2 = db[f];
    #pragma unroll
    for (int j = 0; j < 8; ++j) acc[j] = bb2;
    for (int k = 0; k < NFc; k += 4){
        float w0 = dw[(k+0)*NFc + f];
        float w1 = dw[(k+1)*NFc + f];
        float w2 = dw[(k+2)*NFc + f];
        float w3 = dw[(k+3)*NFc + f];
        #pragma unroll
        for (int j = 0; j < 8; ++j){
            float4 tv = *reinterpret_cast<const float4*>(&ts[j*NFc + k]);
            acc[j] += tv.x*w0 + tv.y*w1 + tv.z*w2 + tv.w*w3;
        }
    }
    #pragma unroll
    for (int j = 0; j < 8; ++j)
        x[(size_t)(a0+j)*NFc + f] += acc[j];
}

// ---------------------------------------------------------------------------
extern "C" void kernel_launch(void* const* d_in, const int* in_sizes, int n_in,
                              void* d_out, int out_size){
    const float* positions = (const float*)d_in[0];
    const float* cell      = (const float*)d_in[1];
    const float* cofs      = (const float*)d_in[2];
    const float* nmask     = (const float*)d_in[3];
    // d_in[4] atom_mask: unused by reference
    const float* emb       = (const float*)d_in[5];
    const float* fw1       = (const float*)d_in[6];
    const float* fb1       = (const float*)d_in[7];
    const float* fw2       = (const float*)d_in[8];
    const float* fb2       = (const float*)d_in[9];
    const float* in2f_w    = (const float*)d_in[10];
    const float* f2out_w   = (const float*)d_in[11];
    const float* f2out_b   = (const float*)d_in[12];
    const float* dense_w   = (const float*)d_in[13];
    const float* dense_b   = (const float*)d_in[14];
    const int*   znum      = (const int*)  d_in[15];
    const int*   nbr       = (const int*)  d_in[16];
    float* x = (float*)d_out;

    static int smem_set = 0;
    if (!smem_set){
        cudaFuncSetAttribute(k_conv_m, cudaFuncAttributeMaxDynamicSharedMemorySize, SM_TOTB);
        smem_set = 1;
    }

    k_prep<<<(BANB + 255)/256, 256>>>(positions, cell, cofs, nmask, nbr);
    k_wt  <<<(NIc*8*16*32*4 + 255)/256, 256>>>(fw2);
    k_embed<<<(BA*NABc + 255)/256, 256>>>(emb, znum, x);

    for (int i = 0; i < NIc; ++i){
        k_y     <<<BA/8, NFc>>>(x, in2f_w + (size_t)i*NABc*NFc);
        k_conv_m<<<BA,   128, SM_TOTB>>>(i,
                              fw1 + (size_t)i*NGc*NFc, fb1 + (size_t)i*NFc,
                              fb2 + (size_t)i*NFc,
                              nbr, nmask);
        k_out   <<<BA/8, NFc>>>(f2out_w + (size_t)i*NFc*NABc, f2out_b + (size_t)i*NABc,
                              dense_w + (size_t)i*NABc*NABc, dense_b + (size_t)i*NABc,
                              x);
    }
}

// round 16
// speedup vs baseline: 2.8574x; 1.8840x over previous
#include <cuda_runtime.h>
#include <cuda_bf16.h>
#include <cstdint>

// Problem constants
#define BB   8
#define AA   1024
#define NBN  64
#define NABc 128
#define NFc  128
#define NGc  25
#define NIc  3
#define BA   (BB*AA)        // 8192
#define BANB (BA*NBN)       // 524288
#define CUTF 5.0f

// Scratch (static device globals — allocation-free)
__device__ float g_fij[BANB*NGc];   // gaussian-smeared distances, [pair][25]
__device__ float g_C[BANB];         // cosine cutoff per pair
__device__ float g_y[BA*NFc];       // y = x @ in2f_w
__device__ float g_agg[BA*NFc];     // CFConv aggregate
// fw2^T in mma A-fragment order, tf32: [i][mtile8][kstep16][lane32][reg4]
__device__ __align__(16) uint32_t g_afh[NIc*8*16*32*4];
// fw1^T in mma A-fragment order, tf32: [i][mtile8][kstep4][lane32][reg4]
__device__ __align__(16) uint32_t g_af1[NIc*8*4*32*4];

__device__ __forceinline__ float sspf(float x){
    // accurate shifted softplus (used in k_out)
    return fmaxf(x, 0.f) + log1pf(expf(-fabsf(x))) - 0.69314718055994530942f;
}
__device__ __forceinline__ float sspf_fast(float x){
    // MUFU-based shifted softplus (rel err ~1e-6)
    float e = __expf(-fabsf(x));
    return fmaxf(x, 0.f) + __logf(1.0f + e) - 0.69314718055994530942f;
}
__device__ __forceinline__ uint32_t f2t(float x){
    uint32_t r; asm("cvt.rna.tf32.f32 %0, %1;" : "=r"(r) : "f"(x)); return r;
}
// D(16x8) += A(16x8 row, tf32) * B(8x8 col, tf32)   [family-wide sm_80+ mma]
__device__ __forceinline__ void mma8(float* d, const uint32_t* a, const uint32_t* b){
    asm volatile(
        "mma.sync.aligned.m16n8k8.row.col.f32.tf32.tf32.f32 "
        "{%0,%1,%2,%3}, {%4,%5,%6,%7}, {%8,%9}, {%0,%1,%2,%3};"
        : "+f"(d[0]), "+f"(d[1]), "+f"(d[2]), "+f"(d[3])
        : "r"(a[0]), "r"(a[1]), "r"(a[2]), "r"(a[3]), "r"(b[0]), "r"(b[1]));
}
// BH fragment index for element (n, k) — verified convention from round 15
__device__ __forceinline__ int bhidx(int n, int k){
    return ((((n >> 3)*16 + (k >> 3))*32 + (n & 7)*4 + (k & 3)) << 1) + ((k >> 2) & 1);
}

// ---------------------------------------------------------------------------
// k_prep: distances, gaussian smearing, cosine cutoff
// ---------------------------------------------------------------------------
__global__ void k_prep(const float* __restrict__ pos,
                       const float* __restrict__ cell,
                       const float* __restrict__ cofs,
                       const float* __restrict__ nmask,
                       const int*   __restrict__ nbr){
    int p = blockIdx.x * blockDim.x + threadIdx.x;
    if (p >= BANB) return;
    int b = p / (AA*NBN);
    int a = (p / NBN) % AA;
    int j = nbr[p];
    const float* pi = pos + ((size_t)b*AA + a)*3;
    const float* pj = pos + ((size_t)b*AA + j)*3;
    const float* of = cofs + (size_t)p*3;
    const float* cl = cell + (size_t)b*9;
    float dx = pj[0] + of[0]*cl[0] + of[1]*cl[3] + of[2]*cl[6] - pi[0];
    float dy = pj[1] + of[0]*cl[1] + of[1]*cl[4] + of[2]*cl[7] - pi[1];
    float dz = pj[2] + of[0]*cl[2] + of[1]*cl[5] + of[2]*cl[8] - pi[2];
    float d2 = dx*dx + dy*dy + dz*dz;
    float m  = nmask[p];
    float r  = sqrtf(m > 0.f ? d2 : 1.0f) * m;
    float C  = (r < CUTF) ? 0.5f*(cosf(r*(3.14159265358979323846f/CUTF)) + 1.f) : 0.f;
    g_C[p] = C;
    const float width = CUTF / (float)(NGc-1);
    const float coeff = -0.5f / (width*width);
    #pragma unroll
    for (int g = 0; g < NGc; ++g){
        float d = r - (float)g*width;
        g_fij[(size_t)p*NGc + g] = expf(coeff*d*d);
    }
}

// ---------------------------------------------------------------------------
// k_wt: fw2 -> A-fragments (fw2^T, 128f x 128k), tf32.
// a0:(row,col) a1:(row+8,col) a2:(row,col+4) a3:(row+8,col+4);
// row = mt*16 + l>>2, col = s*8 + (l&3). idx = (((i*8+m)*16+s)*32+l)*4+r.
// ---------------------------------------------------------------------------
__global__ void k_wt(const float* __restrict__ fw2){
    int idx = blockIdx.x*blockDim.x + threadIdx.x;
    if (idx >= NIc*8*16*32*4) return;
    int r = idx & 3;
    int l = (idx >> 2) & 31;
    int s = (idx >> 7) & 15;
    int m = (idx >> 11) & 7;
    int i = idx >> 14;
    int f = m*16 + (l >> 2) + (r & 1)*8;     // A row = filter index
    int k = s*8 + (l & 3) + ((r & 2) ? 4 : 0); // A col = k index
    g_afh[idx] = f2t(fw2[((size_t)i*NFc + k)*NFc + f]);
}

// ---------------------------------------------------------------------------
// k_wt1: fw1 -> A-fragments (fw1^T, 128k x 32g, g>=25 zero), tf32.
// idx = (((i*8+m)*4+s)*32+l)*4+r
// ---------------------------------------------------------------------------
__global__ void k_wt1(const float* __restrict__ fw1){
    int idx = blockIdx.x*blockDim.x + threadIdx.x;
    if (idx >= NIc*8*4*32*4) return;
    int r = idx & 3;
    int l = (idx >> 2) & 31;
    int s = (idx >> 7) & 3;
    int m = (idx >> 9) & 7;
    int i = idx >> 12;
    int k = m*16 + (l >> 2) + (r & 1)*8;       // A row = filter-k index
    int g = s*8 + (l & 3) + ((r & 2) ? 4 : 0); // A col = gaussian index
    float v = (g < NGc) ? fw1[((size_t)i*NGc + g)*NFc + k] : 0.f;
    g_af1[idx] = f2t(v);
}

// ---------------------------------------------------------------------------
// k_embed: x = emb[atomic_numbers]
// ---------------------------------------------------------------------------
__global__ void k_embed(const float* __restrict__ emb,
                        const int*   __restrict__ z,
                        float* __restrict__ x){
    int i = blockIdx.x * blockDim.x + threadIdx.x;
    if (i >= BA*NABc) return;
    int a = i / NABc;
    int f = i % NABc;
    x[i] = emb[(size_t)z[a]*NABc + f];
}

// ---------------------------------------------------------------------------
// k_y: y = x @ in2f_w   (8192,128)@(128,128), 8 atoms per block
// ---------------------------------------------------------------------------
__global__ void __launch_bounds__(NFc) k_y(const float* __restrict__ x,
                                           const float* __restrict__ w){
    __shared__ __align__(16) float xs[8*NFc];
    int a0 = blockIdx.x * 8;
    int f  = threadIdx.x;
    for (int t = f; t < 8*NFc; t += NFc) xs[t] = x[(size_t)a0*NFc + t];
    __syncthreads();
    float acc[8];
    #pragma unroll
    for (int j = 0; j < 8; ++j) acc[j] = 0.f;
    for (int k = 0; k < NFc; k += 4){
        float w0 = w[(k+0)*NFc + f];
        float w1 = w[(k+1)*NFc + f];
        float w2 = w[(k+2)*NFc + f];
        float w3 = w[(k+3)*NFc + f];
        #pragma unroll
        for (int j = 0; j < 8; ++j){
            float4 xv = *reinterpret_cast<const float4*>(&xs[j*NFc + k]);
            acc[j] += xv.x*w0 + xv.y*w1 + xv.z*w2 + xv.w*w3;
        }
    }
    #pragma unroll
    for (int j = 0; j < 8; ++j)
        g_y[(size_t)(a0+j)*NFc + f] = acc[j];
}

// ---------------------------------------------------------------------------
// k_conv_m: CFConv, BOTH GEMMs on tf32 HMMA.
// 1 block = 1 atom (64 neighbor rows), 128 threads / 4 warps.
//  step1 (HMMA): D1[k][n] = sum_g fw1t[k][g]*F[n][g]  (M=128,N=64,K=32)
//                repack: BH frag(n,k) = tf32(ssp(D1 + b1[k]))
//  step2 (HMMA): D[f][n]  = sum_k fw2t[f][k]*H[n][k]  (M=128,N=64,K=128)
//  stage:        D -> Ws[n][f] (aliased over dead BH)
//  epilogue:     agg[f] = sum_n (D+b2)*C[n]*M[n]*y[nbr[n]][f]
// smem: Ff 8192 | CM 256 | NS 256 | BH 32768 (SmF staging + Ws alias) = 41472 B
// ---------------------------------------------------------------------------
#define SB_FF   0
#define SB_CM   8192
#define SB_NS   8448
#define SB_BH   8704
#define SM_TOTB (SB_BH + 32768)

__global__ void __launch_bounds__(128) k_conv_m(int inter,
        const float* __restrict__ fb1, const float* __restrict__ fb2,
        const int*   __restrict__ nbr, const float* __restrict__ nmask){
    extern __shared__ char smc[];
    uint32_t* Ff  = (uint32_t*)(smc + SB_FF);
    float*    CM  = (float*)(smc + SB_CM);
    int*      NS  = (int*)(smc + SB_NS);
    uint32_t* BH  = (uint32_t*)(smc + SB_BH);
    float*    SmF = (float*)(smc + SB_BH);    // staging alias (dead before BH writes)
    float*    Ws  = (float*)(smc + SB_BH);    // stage alias (after BH dead)

    int tid = threadIdx.x, wid = tid >> 5, lane = tid & 31;
    int ba = blockIdx.x;                 // flat (b,a)
    int b  = ba >> 10;
    size_t p0 = (size_t)ba * NBN;

    // Stage gaussians linearly + C*mask + neighbor idx
    for (int t = tid; t < NBN*NGc; t += 128)
        SmF[t] = g_fij[p0*NGc + t];
    if (tid < NBN){
        CM[tid] = g_C[p0 + tid] * nmask[p0 + tid];
        NS[tid] = nbr[p0 + tid];
    }
    __syncthreads();

    // Scatter F into B-fragment layout (tf32), 2048 elements
    #pragma unroll
    for (int e = tid; e < 2048; e += 128){
        int rb = e & 1, l = (e >> 1) & 31, s = (e >> 6) & 3, nt = e >> 8;
        int n = nt*8 + (l >> 2);
        int g = s*8 + (l & 3) + rb*4;
        float v = (g < NGc) ? SmF[n*NGc + g] : 0.f;
        Ff[e] = f2t(v);
    }
    __syncthreads();   // after this, SmF dead; Ff live

    // ---- step 1 HMMA: D1[k][n], warp wid -> mtiles {2w,2w+1} ----
    float acc1[2][8][4];
    #pragma unroll
    for (int mt = 0; mt < 2; ++mt)
        #pragma unroll
        for (int nt = 0; nt < 8; ++nt)
            #pragma unroll
            for (int r = 0; r < 4; ++r) acc1[mt][nt][r] = 0.f;

    const uint4* A1 = reinterpret_cast<const uint4*>(g_af1 + (size_t)inter*4096);
    #pragma unroll
    for (int s = 0; s < 4; ++s){
        uint4 a1[2];
        #pragma unroll
        for (int mt = 0; mt < 2; ++mt)
            a1[mt] = A1[((2*wid + mt)*4 + s)*32 + lane];
        #pragma unroll
        for (int nt = 0; nt < 8; ++nt){
            uint2 bv = *reinterpret_cast<const uint2*>(&Ff[((nt*4 + s)*32 + lane)*2]);
            uint32_t br[2] = {bv.x, bv.y};
            #pragma unroll
            for (int mt = 0; mt < 2; ++mt)
                mma8(acc1[mt][nt], &a1[mt].x, br);
        }
    }

    // ---- repack: bias + ssp + tf32 -> BH fragment layout ----
    {
        int g4 = lane >> 2, t4 = lane & 3;
        #pragma unroll
        for (int mt = 0; mt < 2; ++mt){
            int kA = (2*wid + mt)*16 + g4;
            float bA = __ldg(fb1 + kA);
            float bB = __ldg(fb1 + kA + 8);
            #pragma unroll
            for (int nt = 0; nt < 8; ++nt){
                int n0 = nt*8 + t4*2;
                BH[bhidx(n0,   kA  )] = f2t(sspf_fast(acc1[mt][nt][0] + bA));
                BH[bhidx(n0+1, kA  )] = f2t(sspf_fast(acc1[mt][nt][1] + bA));
                BH[bhidx(n0,   kA+8)] = f2t(sspf_fast(acc1[mt][nt][2] + bB));
                BH[bhidx(n0+1, kA+8)] = f2t(sspf_fast(acc1[mt][nt][3] + bB));
            }
        }
    }
    __syncthreads();

    // ---- step 2 HMMA: D[f][n], warp wid -> mtiles {2w,2w+1}, 16 ksteps ----
    float acc[2][8][4];
    #pragma unroll
    for (int mt = 0; mt < 2; ++mt)
        #pragma unroll
        for (int nt = 0; nt < 8; ++nt)
            #pragma unroll
            for (int r = 0; r < 4; ++r) acc[mt][nt][r] = 0.f;

    const uint4* Ah = reinterpret_cast<const uint4*>(g_afh + (size_t)inter*16384);
    #pragma unroll 4
    for (int s = 0; s < 16; ++s){
        uint4 ah[2];
        #pragma unroll
        for (int mt = 0; mt < 2; ++mt)
            ah[mt] = Ah[((2*wid + mt)*16 + s)*32 + lane];
        #pragma unroll
        for (int nt = 0; nt < 8; ++nt){
            uint2 bh = *reinterpret_cast<const uint2*>(&BH[((nt*16 + s)*32 + lane)*2]);
            uint32_t bhr[2] = {bh.x, bh.y};
            #pragma unroll
            for (int mt = 0; mt < 2; ++mt)
                mma8(acc[mt][nt], &ah[mt].x, bhr);
        }
    }
    __syncthreads();   // all warps done reading BH before aliasing as Ws

    // ---- stage D into Ws[n][f] ----
    {
        int g4 = lane >> 2, t4 = lane & 3;
        #pragma unroll
        for (int mt = 0; mt < 2; ++mt){
            int f = 32*wid + mt*16 + g4;
            #pragma unroll
            for (int nt = 0; nt < 8; ++nt){
                int n = nt*8 + t4*2;
                Ws[n*NFc + f]         = acc[mt][nt][0];
                Ws[(n+1)*NFc + f]     = acc[mt][nt][1];
                Ws[n*NFc + f + 8]     = acc[mt][nt][2];
                Ws[(n+1)*NFc + f + 8] = acc[mt][nt][3];
            }
        }
    }
    __syncthreads();

    // ---- epilogue: thread = f; coalesced y gathers ----
    float b2 = fb2[tid];
    const float* yb = g_y + (size_t)b*AA*NFc;
    float agg = 0.f;
    #pragma unroll 4
    for (int n = 0; n < NBN; ++n){
        float w = (Ws[n*NFc + tid] + b2) * CM[n];
        agg += w * yb[(size_t)NS[n]*NFc + tid];
    }
    g_agg[(size_t)ba*NFc + tid] = agg;
}

// ---------------------------------------------------------------------------
// k_out: v = ssp(agg @ f2out_w + f2out_b) @ dense_w + dense_b;  x += v
// ---------------------------------------------------------------------------
__global__ void __launch_bounds__(NFc) k_out(const float* __restrict__ f2w,
                                             const float* __restrict__ f2b,
                                             const float* __restrict__ dw,
                                             const float* __restrict__ db,
                                             float* __restrict__ x){
    __shared__ __align__(16) float as_[8*NFc];
    __shared__ __align__(16) float ts[8*NFc];
    int a0 = blockIdx.x * 8;
    int f  = threadIdx.x;
    for (int t = f; t < 8*NFc; t += NFc) as_[t] = g_agg[(size_t)a0*NFc + t];
    __syncthreads();

    float acc[8];
    float bb1 = f2b[f];
    #pragma unroll
    for (int j = 0; j < 8; ++j) acc[j] = bb1;
    for (int k = 0; k < NFc; k += 4){
        float w0 = f2w[(k+0)*NFc + f];
        float w1 = f2w[(k+1)*NFc + f];
        float w2 = f2w[(k+2)*NFc + f];
        float w3 = f2w[(k+3)*NFc + f];
        #pragma unroll
        for (int j = 0; j < 8; ++j){
            float4 av = *reinterpret_cast<const float4*>(&as_[j*NFc + k]);
            acc[j] += av.x*w0 + av.y*w1 + av.z*w2 + av.w*w3;
        }
    }
    #pragma unroll
    for (int j = 0; j < 8; ++j) ts[j*NFc + f] = sspf(acc[j]);
    __syncthreads();

    float bb2 = db[f];
    #pragma unroll
    for (int j = 0; j < 8; ++j) acc[j] = bb2;
    for (int k = 0; k < NFc; k += 4){
        float w0 = dw[(k+0)*NFc + f];
        float w1 = dw[(k+1)*NFc + f];
        float w2 = dw[(k+2)*NFc + f];
        float w3 = dw[(k+3)*NFc + f];
        #pragma unroll
        for (int j = 0; j < 8; ++j){
            float4 tv = *reinterpret_cast<const float4*>(&ts[j*NFc + k]);
            acc[j] += tv.x*w0 + tv.y*w1 + tv.z*w2 + tv.w*w3;
        }
    }
    #pragma unroll
    for (int j = 0; j < 8; ++j)
        x[(size_t)(a0+j)*NFc + f] += acc[j];
}

// ---------------------------------------------------------------------------
extern "C" void kernel_launch(void* const* d_in, const int* in_sizes, int n_in,
                              void* d_out, int out_size){
    const float* positions = (const float*)d_in[0];
    const float* cell      = (const float*)d_in[1];
    const float* cofs      = (const float*)d_in[2];
    const float* nmask     = (const float*)d_in[3];
    // d_in[4] atom_mask: unused by reference
    const float* emb       = (const float*)d_in[5];
    const float* fw1       = (const float*)d_in[6];
    const float* fb1       = (const float*)d_in[7];
    const float* fw2       = (const float*)d_in[8];
    const float* fb2       = (const float*)d_in[9];
    const float* in2f_w    = (const float*)d_in[10];
    const float* f2out_w   = (const float*)d_in[11];
    const float* f2out_b   = (const float*)d_in[12];
    const float* dense_w   = (const float*)d_in[13];
    const float* dense_b   = (const float*)d_in[14];
    const int*   znum      = (const int*)  d_in[15];
    const int*   nbr       = (const int*)  d_in[16];
    float* x = (float*)d_out;

    static int smem_set = 0;
    if (!smem_set){
        cudaFuncSetAttribute(k_conv_m, cudaFuncAttributeMaxDynamicSharedMemorySize, SM_TOTB);
        smem_set = 1;
    }

    k_prep<<<(BANB + 255)/256, 256>>>(positions, cell, cofs, nmask, nbr);
    k_wt  <<<(NIc*8*16*32*4 + 255)/256, 256>>>(fw2);
    k_wt1 <<<(NIc*8*4*32*4 + 255)/256, 256>>>(fw1);
    k_embed<<<(BA*NABc + 255)/256, 256>>>(emb, znum, x);

    for (int i = 0; i < NIc; ++i){
        k_y     <<<BA/8, NFc>>>(x, in2f_w + (size_t)i*NABc*NFc);
        k_conv_m<<<BA,   128, SM_TOTB>>>(i,
                              fb1 + (size_t)i*NFc, fb2 + (size_t)i*NFc,
                              nbr, nmask);
        k_out   <<<BA/8, NFc>>>(f2out_w + (size_t)i*NFc*NABc, f2out_b + (size_t)i*NABc,
                              dense_w + (size_t)i*NABc*NABc, dense_b + (size_t)i*NABc,
                              x);
    }
}